// round 12
// baseline (speedup 1.0000x reference)
#include <cuda_runtime.h>

// AdderConv + BatchNorm2d (training stats): x[8,32,28,28], W[64,32,3,3], pad=1.
// out[n,o,h,w] = -sum_k |x - w|, then per-channel BN (biased var, eps=1e-5).
//
// SINGLE fused kernel, grid (4 spatial tiles, 8 oc-groups, 8 n) = 256 blocks
// x 512 threads. IN-BLOCK K-SPLIT: warps 0-7 (team 0) accumulate input channels
// 0-15, warps 8-15 (team 1) channels 16-31, for the same 196 pixels x 8 ocs.
// Teams combine via smem (reuse of x tile). Then R11's epilogue: block stats,
// replay-safe ticket barrier across the 256 co-resident blocks, per-channel
// scale/bias, in-register normalize, single output write.
// Rationale: R11 measured issue-bound at 45% eff with 16 warps/SM (grid-limited
// occupancy). Same total instructions at 32 warps/SM -> ~65% eff -> ~16-17us.

__device__ float g_psum[64 * 32];     // [oc][pidx], pidx = n*4 + s
__device__ float g_psumsq[64 * 32];
__device__ unsigned g_ctr;            // monotonic ticket counter (never reset)

__device__ __forceinline__ unsigned long long add_f32x2(unsigned long long a,
                                                        unsigned long long b) {
    unsigned long long r;
    asm("add.rn.f32x2 %0, %1, %2;" : "=l"(r) : "l"(a), "l"(b));
    return r;
}

__global__ __launch_bounds__(512) void fused_kernel(
    const float* __restrict__ x, const float* __restrict__ W,
    const float* __restrict__ gamma, const float* __restrict__ beta,
    float* __restrict__ out)
{
    __shared__ __align__(16) float xs[32 * 256];       // 32KB; reused for combine
    __shared__ __align__(16) float nws[288 * 8];       // 9KB
    __shared__ float red[16][8];                       // team-0 warp partials
    __shared__ float2 scb[8];                          // per-oc {scale, bias}

    const int s   = blockIdx.x;   // spatial tile 0..3
    const int ocg = blockIdx.y;   // 0..7 (8 output channels each)
    const int n   = blockIdx.z;   // 0..7
    const int th  = (s >> 1) * 14;
    const int tw  = (s & 1) * 14;
    const int tid = threadIdx.x;
    const int wid = tid >> 5;     // 0..15
    const int lid = tid & 31;
    const int team = tid >> 8;    // 0: channels 0-15, 1: channels 16-31
    const int p   = tid & 255;    // pixel slot within team

    // ---- prologue: 512 threads cooperatively load x tile + negated weights ----
    const float* xb = x + n * (32 * 28 * 28);
    #pragma unroll
    for (int i = tid; i < 32 * 256; i += 512) {
        int c = i >> 8, cell = i & 255;
        int r = cell >> 4, col = cell & 15;
        int gh = th - 1 + r, gw = tw - 1 + col;
        float v = 0.f;
        if ((unsigned)gh < 28u && (unsigned)gw < 28u)
            v = xb[c * 784 + gh * 28 + gw];
        xs[i] = v;
    }
    const float* Wb = W + ocg * (8 * 288);
    #pragma unroll
    for (int i = tid; i < 8 * 288; i += 512) {
        int o = i & 7, k = i >> 3;
        nws[k * 8 + o] = -Wb[o * 288 + k];
    }
    __syncthreads();

    // ---- mainloop: each team does 16 channels for its pixel ----
    unsigned long long acc0 = 0ull, acc1 = 0ull, acc2 = 0ull, acc3 = 0ull;
    if (p < 196) {
        const int ph = p / 14;
        const int pw = p - ph * 14;
        const float* xp = xs + (team * 16) * 256 + ph * 16 + pw;
        const ulonglong2* wp = (const ulonglong2*)nws + (team * 16) * 9 * 2;

        #pragma unroll 1
        for (int c = 0; c < 16; ++c) {
            const float* xc = xp + c * 256;
            #pragma unroll
            for (int r = 0; r < 3; ++r) {
                #pragma unroll
                for (int q = 0; q < 3; ++q) {
                    float xv = xc[r * 16 + q];
                    unsigned long long xx;
                    asm("mov.b64 %0, {%1, %1};" : "=l"(xx) : "r"(__float_as_uint(xv)));
                    const ulonglong2* w4 = wp + (c * 9 + r * 3 + q) * 2;
                    ulonglong2 wA = w4[0];
                    ulonglong2 wB = w4[1];
                    unsigned long long d0 = add_f32x2(xx, wA.x) & 0x7FFFFFFF7FFFFFFFULL;
                    unsigned long long d1 = add_f32x2(xx, wA.y) & 0x7FFFFFFF7FFFFFFFULL;
                    unsigned long long d2 = add_f32x2(xx, wB.x) & 0x7FFFFFFF7FFFFFFFULL;
                    unsigned long long d3 = add_f32x2(xx, wB.y) & 0x7FFFFFFF7FFFFFFFULL;
                    acc0 = add_f32x2(acc0, d0);
                    acc1 = add_f32x2(acc1, d1);
                    acc2 = add_f32x2(acc2, d2);
                    acc3 = add_f32x2(acc3, d3);
                }
            }
        }
    }

    // ---- unpack this team's positive half-sums ----
    float val[8];
    {
        unsigned long long a[4] = {acc0, acc1, acc2, acc3};
        #pragma unroll
        for (int j = 0; j < 4; ++j) {
            val[2 * j]     = __uint_as_float((unsigned)(a[j] & 0xFFFFFFFFu));
            val[2 * j + 1] = __uint_as_float((unsigned)(a[j] >> 32));
        }
    }

    // ---- combine halves via smem (reuse xs; mainloop reads are done) ----
    float* comb = xs;                    // 8 x 196 floats
    __syncthreads();
    if (team == 1 && p < 196) {
        #pragma unroll
        for (int j = 0; j < 8; ++j) comb[j * 196 + p] = val[j];
    }
    __syncthreads();
    if (team == 0 && p < 196) {
        #pragma unroll
        for (int j = 0; j < 8; ++j) val[j] += comb[j * 196 + p];
    }

    // ---- block stats (team 0 only): warp shfl reduce + 8-warp fold ----
    if (team == 0) {
        float sv[8], qv[8];
        #pragma unroll
        for (int j = 0; j < 8; ++j) {
            float v = (p < 196) ? val[j] : 0.f;
            sv[j] = -v;                  // out value is -val
            qv[j] = v * v;
        }
        #pragma unroll
        for (int d = 16; d > 0; d >>= 1) {
            #pragma unroll
            for (int j = 0; j < 8; ++j) {
                sv[j] += __shfl_down_sync(0xFFFFFFFFu, sv[j], d);
                qv[j] += __shfl_down_sync(0xFFFFFFFFu, qv[j], d);
            }
        }
        if (lid == 0) {
            #pragma unroll
            for (int j = 0; j < 8; ++j) {
                red[j][wid]     = sv[j];
                red[j + 8][wid] = qv[j];
            }
        }
    }
    __syncthreads();

    const int pidx = n * 4 + s;
    if (tid < 16) {
        float t = red[tid][0];
        #pragma unroll
        for (int u = 1; u < 8; ++u) t += red[tid][u];
        if (tid < 8) g_psum[(ocg * 8 + tid) * 32 + pidx] = t;
        else         g_psumsq[(ocg * 8 + (tid - 8)) * 32 + pidx] = t;
    }
    __syncthreads();

    // ---- replay-safe ticket barrier over the 256 co-resident blocks ----
    if (tid == 0) {
        __threadfence();
        unsigned arrival = atomicAdd(&g_ctr, 1u);
        unsigned target = ((arrival >> 8) + 1u) << 8;   // this launch's 256th ticket
        while ((int)(*(volatile unsigned*)&g_ctr - target) < 0) __nanosleep(64);
        __threadfence();
    }
    __syncthreads();

    // ---- per-channel stats: warp w (0..7) folds oc (ocg*8+w)'s 32 partials ----
    if (wid < 8) {
        const int oc = ocg * 8 + wid;
        float ss = *(volatile float*)&g_psum[oc * 32 + lid];
        float qq = *(volatile float*)&g_psumsq[oc * 32 + lid];
        #pragma unroll
        for (int d = 16; d > 0; d >>= 1) {
            ss += __shfl_down_sync(0xFFFFFFFFu, ss, d);
            qq += __shfl_down_sync(0xFFFFFFFFu, qq, d);
        }
        if (lid == 0) {
            float mean = ss * (1.f / 6272.f);
            float var  = qq * (1.f / 6272.f) - mean * mean;
            float sc = gamma[oc] * rsqrtf(var + 1e-5f);
            scb[wid] = make_float2(sc, beta[oc] - mean * sc);
        }
    }
    __syncthreads();

    // ---- normalize in registers (team 0), single global write ----
    if (team == 0 && p < 196) {
        const int ph = p / 14;
        const int pw = p - ph * 14;
        const int gh = th + ph, gw = tw + pw;
        float* ob = out + (n * 64 + ocg * 8) * 784 + gh * 28 + gw;
        #pragma unroll
        for (int j = 0; j < 8; ++j) {
            float2 c = scb[j];
            ob[j * 784] = fmaf(val[j], -c.x, c.y);   // y = (-val)*sc + bi
        }
    }
}

extern "C" void kernel_launch(void* const* d_in, const int* in_sizes, int n_in,
                              void* d_out, int out_size) {
    const float* x     = (const float*)d_in[0];  // [8,32,28,28]
    const float* W     = (const float*)d_in[1];  // [64,32,3,3]
    const float* gamma = (const float*)d_in[2];  // [64]
    const float* beta  = (const float*)d_in[3];  // [64]
    float* out = (float*)d_out;                  // [8,64,28,28]

    dim3 g1(4, 8, 8);
    fused_kernel<<<g1, 512>>>(x, W, gamma, beta, out);
}